// round 5
// baseline (speedup 1.0000x reference)
#include <cuda_runtime.h>
#include <cuda_bf16.h>
#include <cstdint>

// ---------------- problem constants ----------------
#define BB    2048
#define F1N   10
#define F2N   25
#define NTOK  261
#define XROW4 32            // float4 per 128-float x row

// ---------------- scratch (device globals, allocation-free) ----------------
__device__ __align__(16) __nv_bfloat16 g_A2h[BB * 512];
__device__ __align__(16) __nv_bfloat16 g_A2l[BB * 512];
__device__ __align__(16) __nv_bfloat16 g_W1hT[256 * 256];
__device__ __align__(16) __nv_bfloat16 g_W1lT[256 * 256];
__device__ __align__(16) __nv_bfloat16 g_W2hT[256 * 512];
__device__ __align__(16) __nv_bfloat16 g_W2lT[256 * 512];

// ---------------- PTX helpers (base sm_100-safe) ----------------
__device__ __forceinline__ uint32_t smem_u32(const void* p) {
    uint32_t a;
    asm("{ .reg .u64 t; cvta.to.shared.u64 t, %1; cvt.u32.u64 %0, t; }" : "=r"(a) : "l"(p));
    return a;
}
__device__ __forceinline__ void cp16(uint32_t s, const void* g) {
    asm volatile("cp.async.cg.shared.global [%0], [%1], 16;" :: "r"(s), "l"(g));
}
#define CP_COMMIT() asm volatile("cp.async.commit_group;" ::: "memory")
#define CP_WAIT(n)  asm volatile("cp.async.wait_group %0;" :: "n"(n) : "memory")

__device__ __forceinline__ void ldsm4(uint32_t* r, uint32_t addr) {
    asm volatile("ldmatrix.sync.aligned.m8n8.x4.shared.b16 {%0,%1,%2,%3}, [%4];"
                 : "=r"(r[0]), "=r"(r[1]), "=r"(r[2]), "=r"(r[3]) : "r"(addr));
}
__device__ __forceinline__ void mma16816(float* c, const uint32_t* a, const uint32_t* b) {
    asm volatile(
        "mma.sync.aligned.m16n8k16.row.col.f32.bf16.bf16.f32 "
        "{%0,%1,%2,%3}, {%4,%5,%6,%7}, {%8,%9}, {%0,%1,%2,%3};"
        : "+f"(c[0]), "+f"(c[1]), "+f"(c[2]), "+f"(c[3])
        : "r"(a[0]), "r"(a[1]), "r"(a[2]), "r"(a[3]), "r"(b[0]), "r"(b[1]));
}

// ---------------- bf16 split helpers ----------------
__device__ __forceinline__ void split1(float w, unsigned short& h, unsigned short& l) {
    __nv_bfloat16 hb = __float2bfloat16_rn(w);
    float r = w - __bfloat162float(hb);
    __nv_bfloat16 lb = __float2bfloat16_rn(r);
    h = __bfloat16_as_ushort(hb);
    l = __bfloat16_as_ushort(lb);
}
__device__ __forceinline__ void split_store2(__nv_bfloat16* H, __nv_bfloat16* L,
                                             size_t idx, float a, float b) {
    unsigned short h0, l0, h1, l1;
    split1(a, h0, l0);
    split1(b, h1, l1);
    *reinterpret_cast<uint32_t*>(H + idx) = (uint32_t)h0 | ((uint32_t)h1 << 16);
    *reinterpret_cast<uint32_t*>(L + idx) = (uint32_t)l0 | ((uint32_t)l1 << 16);
}

// ---------------- K0: weight transpose + split ----------------
__global__ void k_convw(const float* __restrict__ W1, const float* __restrict__ W2) {
    int i = blockIdx.x * blockDim.x + threadIdx.x;
    if (i < 256 * 256) {
        int n = i >> 8, k = i & 255;
        unsigned short h, l;
        split1(W1[k * 256 + n], h, l);
        g_W1hT[n * 256 + k] = __ushort_as_bfloat16(h);
        g_W1lT[n * 256 + k] = __ushort_as_bfloat16(l);
    } else {
        int j = i - 256 * 256;
        if (j >= 256 * 512) return;
        int n = j >> 9, k = j & 511;
        unsigned short h, l;
        split1(W2[k * 256 + n], h, l);
        g_W2hT[n * 512 + k] = __ushort_as_bfloat16(h);
        g_W2lT[n * 512 + k] = __ushort_as_bfloat16(l);
    }
}

// ---------------- fused1: reduce + GEMM1 + pool, A never hits DRAM ----------------
// Tile: BM=96 rows (8 groups x 12: [h0row, 10 h1rows, dummy]), BN=256 (full N).
// 768 threads = 24 warps (6 M x 4 N), warp tile 16x64. K = 4 chunks of 64.
// smem: Ah(12K) Al(12K) Bh(32K) Bl(32K) msum(4K); epilogue reuses all as fp32 [96][258].
static constexpr int AH_OFF = 0;
static constexpr int AL_OFF = 12288;
static constexpr int BH_OFF = 24576;
static constexpr int BL_OFF = 57344;
static constexpr int MS_OFF = 90112;              // 2 x 8 x 64 floats
static constexpr int SROW   = 258;                // epilogue fp32 row stride
static constexpr int SMEM_F = 96 * SROW * 4 + 256;  // 99328

__global__ __launch_bounds__(768)
void fused1(const float4* __restrict__ x4, const float* __restrict__ bias) {
    extern __shared__ char smem[];
    const uint32_t sb = smem_u32(smem);
    float* msum = reinterpret_cast<float*>(smem + MS_OFF);
    const int tid = threadIdx.x, wid = tid >> 5, lane = tid & 31;
    const int b0 = blockIdx.x * 8;
    const int wm = (wid >> 2) * 16;      // 0..80
    const int wn = (wid & 3) * 64;       // 0..192

    float acc[8][4];
#pragma unroll
    for (int j = 0; j < 8; j++)
#pragma unroll
        for (int q = 0; q < 4; q++) acc[j][q] = 0.f;

    // split-store one float4 into Ah/Al smem tiles at (row, col4) of current chunk
    auto storeA = [&](int row, int col4, float4 v) {
        unsigned short hs[4], ls[4];
        float f[4] = {v.x, v.y, v.z, v.w};
#pragma unroll
        for (int e = 0; e < 4; e++) split1(f[e], hs[e], ls[e]);
        uint2 hv = make_uint2((uint32_t)hs[0] | ((uint32_t)hs[1] << 16),
                              (uint32_t)hs[2] | ((uint32_t)hs[3] << 16));
        uint2 lv = make_uint2((uint32_t)ls[0] | ((uint32_t)ls[1] << 16),
                              (uint32_t)ls[2] | ((uint32_t)ls[3] << 16));
        int cc = col4 >> 1;
        uint32_t off = row * 128 + ((cc ^ (row & 7)) << 4) + (col4 & 1) * 8;
        *reinterpret_cast<uint2*>(smem + AH_OFF + off) = hv;
        *reinterpret_cast<uint2*>(smem + AL_OFF + off) = lv;
    };

    for (int c = 0; c < 4; c++) {
        // ---- B prefetch for this chunk (overlaps A-build) ----
        for (int i = tid; i < 2048; i += 768) {
            int n = i >> 3, cc = i & 7;
            uint32_t sw = n * 128 + ((cc ^ (n & 7)) << 4);
            size_t go = (size_t)n * 256 + c * 64 + cc * 8;
            cp16(sb + BH_OFF + sw, g_W1hT + go);
            cp16(sb + BL_OFF + sw, g_W1lT + go);
        }
        CP_COMMIT();

        // ---- A-tile build for this chunk ----
        if (c < 2) {
            // self-half: copy seed + hop1 cols, accumulate hop1 sum into msum
            if (tid < 128) {
                int col4 = tid & 15, g = tid >> 4;
                const float4* px = x4 + (size_t)(b0 + g) * (NTOK * XROW4) + c * 16 + col4;
                storeA(g * 12, col4, px[0]);                 // seed (token 0)
                float sx = 0.f, sy = 0.f, sz = 0.f, sw = 0.f;
#pragma unroll
                for (int f = 1; f <= F1N; f++) {
                    float4 v = px[(size_t)f * XROW4];
                    storeA(g * 12 + f, col4, v);
                    sx += v.x; sy += v.y; sz += v.z; sw += v.w;
                }
                *reinterpret_cast<float4*>(&msum[((size_t)c * 8 + g) * 64 + col4 * 4]) =
                    make_float4(sx, sy, sz, sw);
                storeA(g * 12 + 11, col4, make_float4(0.f, 0.f, 0.f, 0.f));
            }
        } else {
            // mean-half: stream hop2 (the big 250 MB), row0 from msum, row11 zero
            const int xc4 = (c - 2) * 16;
            for (int i = tid; i < 1536; i += 768) {
                if (i < 1280) {
                    int col4 = i & 15;
                    int f = (i >> 4) % F1N;
                    int g = i / 160;
                    const float4* px = x4 + (size_t)(b0 + g) * (NTOK * XROW4)
                                       + (size_t)(1 + F1N + f * F2N) * XROW4 + xc4 + col4;
                    float sx = 0.f, sy = 0.f, sz = 0.f, sw = 0.f;
#pragma unroll 5
                    for (int k = 0; k < F2N; k++) {
                        float4 v = px[(size_t)k * XROW4];
                        sx += v.x; sy += v.y; sz += v.z; sw += v.w;
                    }
                    const float inv = 1.0f / (float)F2N;
                    storeA(g * 12 + 1 + f, col4,
                           make_float4(sx * inv, sy * inv, sz * inv, sw * inv));
                } else if (i < 1408) {
                    int j = i - 1280;
                    int col4 = j & 15, g = j >> 4;
                    float4 s = *reinterpret_cast<const float4*>(
                        &msum[((size_t)(c - 2) * 8 + g) * 64 + col4 * 4]);
                    const float inv = 1.0f / (float)F1N;
                    storeA(g * 12, col4,
                           make_float4(s.x * inv, s.y * inv, s.z * inv, s.w * inv));
                } else {
                    int j = i - 1408;
                    int col4 = j & 15, g = j >> 4;
                    storeA(g * 12 + 11, col4, make_float4(0.f, 0.f, 0.f, 0.f));
                }
            }
        }
        CP_WAIT(0);
        __syncthreads();

        // ---- MMA for this chunk ----
#pragma unroll
        for (int k16 = 0; k16 < 4; k16++) {
            const int cc = k16 * 2 + (lane >> 4);
            uint32_t ah[4], al[4];
            {
                int r = wm + (lane & 15);
                uint32_t ad = sb + r * 128 + ((cc ^ (r & 7)) << 4);
                ldsm4(ah, ad + AH_OFF);
                ldsm4(al, ad + AL_OFF);
            }
#pragma unroll
            for (int ni = 0; ni < 4; ni++) {
                uint32_t bh[4], bl[4];
                int r = wn + ni * 16 + (lane & 15);
                uint32_t ad = r * 128 + ((cc ^ (r & 7)) << 4);
                ldsm4(bh, sb + BH_OFF + ad);
                ldsm4(bl, sb + BL_OFF + ad);
#pragma unroll
                for (int jj = 0; jj < 2; jj++) {
                    int j = ni * 2 + jj;
                    uint32_t bfh[2] = {bh[jj], bh[jj + 2]};
                    uint32_t bfl[2] = {bl[jj], bl[jj + 2]};
                    mma16816(acc[j], ah, bfh);
                    mma16816(acc[j], ah, bfl);
                    mma16816(acc[j], al, bfh);
                }
            }
        }
        __syncthreads();
    }

    // ---- epilogue: acc (+bias, ReLU) -> smem fp32 [96][SROW] ----
    float* sacc = reinterpret_cast<float*>(smem);
    const int g4 = lane >> 2, q = lane & 3;
#pragma unroll
    for (int j = 0; j < 8; j++) {
        int col = wn + j * 8 + 2 * q;
        float bx = __ldg(bias + col), by = __ldg(bias + col + 1);
        int r = wm + g4;
        sacc[r * SROW + col]           = fmaxf(acc[j][0] + bx, 0.f);
        sacc[r * SROW + col + 1]       = fmaxf(acc[j][1] + by, 0.f);
        sacc[(r + 8) * SROW + col]     = fmaxf(acc[j][2] + bx, 0.f);
        sacc[(r + 8) * SROW + col + 1] = fmaxf(acc[j][3] + by, 0.f);
    }
    __syncthreads();

    // ---- pool: 8 groups x 128 col-pairs -> A2 = [h0 | mean(h1)] split bf16 ----
    for (int i = tid; i < 1024; i += 768) {
        int cp = i & 127, g = i >> 7;
        int ccol = cp * 2;
        const float* rp = sacc + (size_t)(g * 12) * SROW + ccol;
        float h0x = rp[0], h0y = rp[1];
        float sx = 0.f, sy = 0.f;
#pragma unroll
        for (int r = 1; r <= F1N; r++) {
            sx += rp[r * SROW];
            sy += rp[r * SROW + 1];
        }
        size_t ob = (size_t)(b0 + g) * 512 + ccol;
        split_store2(g_A2h, g_A2l, ob, h0x, h0y);
        split_store2(g_A2h, g_A2l, ob + 256, sx * 0.1f, sy * 0.1f);
    }
}

// ---------------- GEMM2: out = A2 @ W2 + b2 (warp-MMA, 3-term split) ----------------
template <int BM, int BN, int KTOT, int WM, int WN>
__global__ __launch_bounds__((BM / WM) * (BN / WN) * 32)
void gemm_mma(const __nv_bfloat16* __restrict__ Ah_g, const __nv_bfloat16* __restrict__ Al_g,
              const __nv_bfloat16* __restrict__ Bh_g, const __nv_bfloat16* __restrict__ Bl_g,
              const float* __restrict__ bias, float* __restrict__ C) {
    constexpr int NTH = (BM / WM) * (BN / WN) * 32;
    constexpr int NCH = KTOT / 64;
    constexpr int SA = BM * 128;
    constexpr int SB = BN * 128;
    constexpr int STAGE = 2 * SA + 2 * SB;
    constexpr int NWN = BN / WN;
    constexpr int MT = WM / 16;
    constexpr int NT8 = WN / 8;
    constexpr int NT16 = WN / 16;

    extern __shared__ char smem[];
    const uint32_t sb = smem_u32(smem);
    const int tid = threadIdx.x, wid = tid >> 5, lane = tid & 31;
    const int row0 = blockIdx.x * BM, col0 = blockIdx.y * BN;
    const int wm = (wid / NWN) * WM;
    const int wn = (wid % NWN) * WN;

    float acc[MT][NT8][4];
#pragma unroll
    for (int mi = 0; mi < MT; mi++)
#pragma unroll
        for (int j = 0; j < NT8; j++)
#pragma unroll
            for (int q = 0; q < 4; q++) acc[mi][j][q] = 0.f;

    auto load_stage = [&](int c, int s) {
        const int kofs = c * 64;
        const uint32_t base = sb + s * STAGE;
#pragma unroll
        for (int i = tid; i < BM * 8; i += NTH) {
            int r = i >> 3, cc = i & 7;
            uint32_t sw = r * 128 + ((cc ^ (r & 7)) << 4);
            size_t go = (size_t)(row0 + r) * KTOT + kofs + cc * 8;
            cp16(base + sw, Ah_g + go);
            cp16(base + SA + sw, Al_g + go);
        }
#pragma unroll
        for (int i = tid; i < BN * 8; i += NTH) {
            int r = i >> 3, cc = i & 7;
            uint32_t sw = r * 128 + ((cc ^ (r & 7)) << 4);
            size_t go = (size_t)(col0 + r) * KTOT + kofs + cc * 8;
            cp16(base + 2 * SA + sw, Bh_g + go);
            cp16(base + 2 * SA + SB + sw, Bl_g + go);
        }
    };

    load_stage(0, 0);
    CP_COMMIT();

    for (int c = 0; c < NCH; c++) {
        const int s = c & 1;
        if (c + 1 < NCH) {
            load_stage(c + 1, s ^ 1);
            CP_COMMIT();
            CP_WAIT(1);
        } else {
            CP_WAIT(0);
        }
        __syncthreads();
        const uint32_t base = sb + s * STAGE;

#pragma unroll
        for (int k16 = 0; k16 < 4; k16++) {
            const int cc = k16 * 2 + (lane >> 4);
            uint32_t ah[MT][4], al[MT][4], bh[NT16][4], bl[NT16][4];
#pragma unroll
            for (int mi = 0; mi < MT; mi++) {
                int r = wm + mi * 16 + (lane & 15);
                uint32_t ad = base + r * 128 + ((cc ^ (r & 7)) << 4);
                ldsm4(ah[mi], ad);
                ldsm4(al[mi], ad + SA);
            }
#pragma unroll
            for (int ni = 0; ni < NT16; ni++) {
                int r = wn + ni * 16 + (lane & 15);
                uint32_t ad = base + 2 * SA + r * 128 + ((cc ^ (r & 7)) << 4);
                ldsm4(bh[ni], ad);
                ldsm4(bl[ni], ad + SB);
            }
#pragma unroll
            for (int mi = 0; mi < MT; mi++)
#pragma unroll
                for (int j = 0; j < NT8; j++) {
                    uint32_t bfh[2] = {bh[j >> 1][j & 1], bh[j >> 1][(j & 1) + 2]};
                    uint32_t bfl[2] = {bl[j >> 1][j & 1], bl[j >> 1][(j & 1) + 2]};
                    mma16816(acc[mi][j], ah[mi], bfh);
                    mma16816(acc[mi][j], ah[mi], bfl);
                    mma16816(acc[mi][j], al[mi], bfh);
                }
        }
        __syncthreads();
    }

    const int g = lane >> 2, q = lane & 3;
#pragma unroll
    for (int mi = 0; mi < MT; mi++)
#pragma unroll
        for (int j = 0; j < NT8; j++) {
            int ccol = col0 + wn + j * 8 + 2 * q;
            float bx = __ldg(bias + ccol), by = __ldg(bias + ccol + 1);
            int r0 = row0 + wm + mi * 16 + g;
            float2 v0 = make_float2(acc[mi][j][0] + bx, acc[mi][j][1] + by);
            float2 v1 = make_float2(acc[mi][j][2] + bx, acc[mi][j][3] + by);
            *reinterpret_cast<float2*>(&C[(size_t)r0 * 256 + ccol]) = v0;
            *reinterpret_cast<float2*>(&C[(size_t)(r0 + 8) * 256 + ccol]) = v1;
        }
}

// ---------------- launch ----------------
static constexpr int SMEM2 = 2 * (2 * 32 * 128 + 2 * 64 * 128);  // 49152

extern "C" void kernel_launch(void* const* d_in, const int* in_sizes, int n_in,
                              void* d_out, int out_size) {
    const float* x  = (const float*)d_in[0];
    const float* W1 = (const float*)d_in[1];
    const float* b1 = (const float*)d_in[2];
    const float* W2 = (const float*)d_in[3];
    const float* b2 = (const float*)d_in[4];
    float* out = (float*)d_out;

    __nv_bfloat16 *a2h, *a2l, *w2h, *w2l;
    cudaGetSymbolAddress((void**)&a2h, g_A2h);
    cudaGetSymbolAddress((void**)&a2l, g_A2l);
    cudaGetSymbolAddress((void**)&w2h, g_W2hT);
    cudaGetSymbolAddress((void**)&w2l, g_W2lT);

    cudaFuncSetAttribute((const void*)fused1,
                         cudaFuncAttributeMaxDynamicSharedMemorySize, SMEM_F);
    cudaFuncSetAttribute((const void*)gemm_mma<32, 64, 512, 32, 16>,
                         cudaFuncAttributeMaxDynamicSharedMemorySize, SMEM2);

    // K0: weight split/transpose
    k_convw<<<(256 * 256 + 256 * 512 + 255) / 256, 256>>>(W1, W2);
    // fused reduce + GEMM1 + pool: writes split A2 directly
    fused1<<<BB / 8, 768, SMEM_F>>>(reinterpret_cast<const float4*>(x), b1);
    // GEMM2: out = A2 @ W2 + b2, M=2048, K=512, grid 64x4 = 256 CTAs
    gemm_mma<32, 64, 512, 32, 16>
        <<<dim3(BB / 32, 4), 128, SMEM2>>>(a2h, a2l, w2h, w2l, b2, out);
}